// round 17
// baseline (speedup 1.0000x reference)
#include <cuda_runtime.h>
#include <cstdint>
#include <math.h>

#define NN 512
#define CS 384
#define CZ 128
#define NH 16
#define HD 24
#define EPS 1e-5f
#define ZST 132   // padded z row stride; 16B-aligned, (ZST/4)%8==1 -> LDS.128 conflict-free
#define KST 28    // padded K/V row stride; 16B-aligned -> LDS.128 conflict-free

typedef unsigned long long u64;

#define FFMA2(d, a, b) asm("fma.rn.f32x2 %0, %1, %2, %0;" : "+l"(d) : "l"(a), "l"(b))
#define PACK2(d, f) asm("mov.b64 %0, {%1, %1};" : "=l"(d) : "r"(__float_as_uint(f)))
#define CP_ASYNC16(dst_u32, src_ptr) \
    asm volatile("cp.async.cg.shared.global [%0], [%1], 16;" :: "r"(dst_u32), "l"(src_ptr))
#define CP_COMMIT() asm volatile("cp.async.commit_group;" ::: "memory")
#define CP_WAIT1()  asm volatile("cp.async.wait_group 1;" ::: "memory")
#define CP_WAIT0()  asm volatile("cp.async.wait_group 0;" ::: "memory")

__device__ __forceinline__ float u64lo(u64 v) { return __uint_as_float((unsigned)v); }
__device__ __forceinline__ float u64hi(u64 v) { return __uint_as_float((unsigned)(v >> 32)); }

// pair_bias smem (floats): 2 z-buffers (64 x ZST) + weights + stats + partials
#define PB_TILE   (64 * ZST)                       // 8448
#define PB_WS     (NH * CZ)                        // 2048
#define PB_STATS  (128)                            // 64 mean + 64 rstd
#define PB_PART   (4 * 32 * 9)                     // 1152
#define PB_SMEM_FLOATS (2 * PB_TILE + PB_WS + PB_STATS + PB_PART)
#define PB_SMEM_BYTES  (PB_SMEM_FLOATS * 4)        // 80896

#define TILES_PER_BLOCK 8

// attn smem
#define ATTN_SMEM_FLOATS (512 * KST * 2 + 64 * KST + 8 * 48)
#define ATTN_SMEM_BYTES  (ATTN_SMEM_FLOATS * 4)    // 123392

// ---------------- scratch ----------------
__device__ float g_an[NN * CS];
__device__ float g_qkvg[NN * 4 * CS];
__device__ float g_bias[(size_t)NH * NN * NN];
__device__ float g_att[NN * CS];
__device__ float g_gwT[NH * CZ];
__device__ float g_colsum[NH];
__device__ float g_cconst[NH];

// ---------------- K1: fused prep + LN(a) + out=bias init ----------------
__global__ void prep_ln_kernel(const float* __restrict__ a, const float* __restrict__ ga,
                               const float* __restrict__ ba,
                               const float* __restrict__ gz, const float* __restrict__ bzln,
                               const float* __restrict__ Wz, const float* __restrict__ bz,
                               const float* __restrict__ bo, float* __restrict__ out) {
    if (blockIdx.x == NN) {
        int c = threadIdx.x;
        float g = gz[c];
        #pragma unroll
        for (int h = 0; h < NH; h++) g_gwT[h * CZ + c] = g * Wz[c * NH + h];
        __syncthreads();
        if (c < NH) {
            float cs = 0.f, ct = bz[c];
            for (int k = 0; k < CZ; k++) {
                cs += g_gwT[c * CZ + k];
                ct += bzln[k] * Wz[k * NH + c];
            }
            g_colsum[c] = cs;
            g_cconst[c] = ct;
        }
        return;
    }
    int row = blockIdx.x, t = threadIdx.x;
    const float* x = a + row * CS;
    float v0 = x[t], v1 = x[t + 128], v2 = x[t + 256];
    float s = v0 + v1 + v2;
    float q = v0 * v0 + v1 * v1 + v2 * v2;
    __shared__ float rs[4], rq[4];
    #pragma unroll
    for (int o = 16; o > 0; o >>= 1) {
        s += __shfl_xor_sync(0xFFFFFFFFu, s, o);
        q += __shfl_xor_sync(0xFFFFFFFFu, q, o);
    }
    if ((t & 31) == 0) { rs[t >> 5] = s; rq[t >> 5] = q; }
    __syncthreads();
    float S = rs[0] + rs[1] + rs[2] + rs[3];
    float Q = rq[0] + rq[1] + rq[2] + rq[3];
    float m = S * (1.f / CS);
    float var = Q * (1.f / CS) - m * m;
    float r = rsqrtf(var + EPS);
    float* o = g_an + row * CS;
    o[t]       = (v0 - m) * r * ga[t]       + ba[t];
    o[t + 128] = (v1 - m) * r * ga[t + 128] + ba[t + 128];
    o[t + 256] = (v2 - m) * r * ga[t + 256] + ba[t + 256];
    float* orow = out + row * CS;
    orow[t]       = bo[t];
    orow[t + 128] = bo[t + 128];
    orow[t + 256] = bo[t + 256];
}

// ---------------- qkvg role body (unchanged) ----------------
__device__ __forceinline__ void qkvg_body(float* smem, int mat, int bm, int bn,
                                          const float* __restrict__ Wq, const float* __restrict__ Wk,
                                          const float* __restrict__ Wv, const float* __restrict__ Wg,
                                          const float* __restrict__ bg) {
    float* As = smem;
    float* Bs = smem + 16 * 64;
    const float* B = (mat == 0) ? Wq : (mat == 1) ? Wk : (mat == 2) ? Wv : Wg;
    int tid = threadIdx.x;
    int tx = tid & 15, ty = tid >> 4;
    int arow = tid >> 2, acol4 = (tid & 3) * 4;
    int brow = tid >> 4, bcol4 = (tid & 15) * 4;
    float acc[4][4] = {};

    for (int k0 = 0; k0 < CS; k0 += 16) {
        float4 av = *(const float4*)(g_an + (bm + arow) * CS + k0 + acol4);
        As[(acol4 + 0) * 64 + arow] = av.x;
        As[(acol4 + 1) * 64 + arow] = av.y;
        As[(acol4 + 2) * 64 + arow] = av.z;
        As[(acol4 + 3) * 64 + arow] = av.w;
        float4 bv = *(const float4*)(B + (k0 + brow) * CS + bn + bcol4);
        *(float4*)&Bs[brow * 68 + bcol4] = bv;
        __syncthreads();
        #pragma unroll
        for (int kk = 0; kk < 16; kk++) {
            float4 a4 = *(const float4*)&As[kk * 64 + ty * 4];
            float4 b4 = *(const float4*)&Bs[kk * 68 + tx * 4];
            float af[4] = {a4.x, a4.y, a4.z, a4.w};
            float bf[4] = {b4.x, b4.y, b4.z, b4.w};
            #pragma unroll
            for (int i = 0; i < 4; i++)
                #pragma unroll
                for (int j = 0; j < 4; j++)
                    acc[i][j] += af[i] * bf[j];
        }
        __syncthreads();
    }
    int colbase = mat * CS + bn + tx * 4;
    #pragma unroll
    for (int i = 0; i < 4; i++) {
        int row = bm + ty * 4 + i;
        float* out = g_qkvg + row * (4 * CS) + colbase;
        #pragma unroll
        for (int j = 0; j < 4; j++) {
            float v = acc[i][j];
            if (mat == 0) v *= 0.2041241452319315f;
            else if (mat == 3) v = 1.f / (1.f + __expf(-(v + bg[bn + tx * 4 + j])));
            out[j] = v;
        }
    }
}

// ---------------- pair_bias: multi-tile, cp.async double-buffered ----------------
__device__ __forceinline__ void pair_bias_stage(uint32_t zbuf_u32, const float* __restrict__ z,
                                                int i, int j0, int t) {
    const float4* src = (const float4*)(z + ((size_t)i * NN + j0) * CZ);
    #pragma unroll
    for (int k = 0; k < 8; k++) {
        int idx = t + 256 * k;           // 0..2047
        int row = idx >> 5, c4 = idx & 31;
        CP_ASYNC16(zbuf_u32 + (row * ZST + c4 * 4) * 4, src + idx);
    }
}

__device__ __forceinline__ void pair_bias_tile_compute(
    const float* zs, const float* ws, float* smean, float* srstd, float* part,
    const float* cs_s, const float* cc_s, int i, int j0) {
    int t = threadIdx.x, lane = t & 31, warp = t >> 5;

    // stats: 64 rows, threads 0..127 (row t>>1, c-half t&1)
    if (t < 128) {
        int row = t >> 1, half = t & 1;
        const float* zr = zs + row * ZST + half * 64;
        float s0 = 0, s1 = 0, s2 = 0, s3 = 0;
        float q0 = 0, q1 = 0, q2 = 0, q3 = 0;
        #pragma unroll
        for (int c = 0; c < 64; c += 4) {
            float4 v = *(const float4*)(zr + c);
            s0 += v.x; s1 += v.y; s2 += v.z; s3 += v.w;
            q0 += v.x * v.x; q1 += v.y * v.y; q2 += v.z * v.z; q3 += v.w * v.w;
        }
        float s = (s0 + s1) + (s2 + s3);
        float q = (q0 + q1) + (q2 + q3);
        s += __shfl_xor_sync(0xFFFFFFFFu, s, 1);
        q += __shfl_xor_sync(0xFFFFFFFFu, q, 1);
        if (half == 0) {
            float m = s * (1.f / 128.f);
            float var = q * (1.f / 128.f) - m * m;
            smean[row] = m;
            srstd[row] = rsqrtf(var + EPS);
        }
    }
    __syncthreads();

    // compute: 2 rows x 4 heads per thread over 64-c half (c-split across warp pairs)
    int hq = warp & 3;
    int cbase = (warp >> 2) * 64;
    const float* z0 = zs + (lane +  0) * ZST + cbase;
    const float* z1 = zs + (lane + 32) * ZST + cbase;
    const float* w0 = ws + (hq * 4 + 0) * CZ + cbase;
    const float* w1 = ws + (hq * 4 + 1) * CZ + cbase;
    const float* w2 = ws + (hq * 4 + 2) * CZ + cbase;
    const float* w3 = ws + (hq * 4 + 3) * CZ + cbase;
    u64 acc2[2][4] = {};
    #pragma unroll 4
    for (int c = 0; c < 64; c += 4) {
        ulonglong2 zp0 = *(const ulonglong2*)(z0 + c);
        ulonglong2 zp1 = *(const ulonglong2*)(z1 + c);
        ulonglong2 wp0 = *(const ulonglong2*)(w0 + c);
        ulonglong2 wp1 = *(const ulonglong2*)(w1 + c);
        ulonglong2 wp2 = *(const ulonglong2*)(w2 + c);
        ulonglong2 wp3 = *(const ulonglong2*)(w3 + c);
        FFMA2(acc2[0][0], zp0.x, wp0.x); FFMA2(acc2[0][0], zp0.y, wp0.y);
        FFMA2(acc2[0][1], zp0.x, wp1.x); FFMA2(acc2[0][1], zp0.y, wp1.y);
        FFMA2(acc2[0][2], zp0.x, wp2.x); FFMA2(acc2[0][2], zp0.y, wp2.y);
        FFMA2(acc2[0][3], zp0.x, wp3.x); FFMA2(acc2[0][3], zp0.y, wp3.y);
        FFMA2(acc2[1][0], zp1.x, wp0.x); FFMA2(acc2[1][0], zp1.y, wp0.y);
        FFMA2(acc2[1][1], zp1.x, wp1.x); FFMA2(acc2[1][1], zp1.y, wp1.y);
        FFMA2(acc2[1][2], zp1.x, wp2.x); FFMA2(acc2[1][2], zp1.y, wp2.y);
        FFMA2(acc2[1][3], zp1.x, wp3.x); FFMA2(acc2[1][3], zp1.y, wp3.y);
    }
    float acc[2][4];
    #pragma unroll
    for (int r = 0; r < 2; r++)
        #pragma unroll
        for (int h = 0; h < 4; h++)
            acc[r][h] = u64lo(acc2[r][h]) + u64hi(acc2[r][h]);

    if (warp >= 4) {
        float* p = part + (hq * 32 + lane) * 9;
        #pragma unroll
        for (int r = 0; r < 2; r++)
            #pragma unroll
            for (int h = 0; h < 4; h++)
                p[r * 4 + h] = acc[r][h];
    }
    __syncthreads();
    if (warp < 4) {
        const float* p = part + (hq * 32 + lane) * 9;
        #pragma unroll
        for (int rr = 0; rr < 2; rr++) {
            int row = lane + rr * 32;
            float m = smean[row], r = srstd[row];
            #pragma unroll
            for (int hh = 0; hh < 4; hh++) {
                int h = hq * 4 + hh;
                float v = acc[rr][hh] + p[rr * 4 + hh];
                g_bias[((size_t)h * NN + i) * NN + j0 + row] =
                    r * (v - m * cs_s[h]) + cc_s[h];
            }
        }
    }
    __syncthreads();  // stats/part reused next tile
}

// ---------------- K2: merged qkvg + pipelined pair_bias ----------------
// blocks 0..191: qkvg; blocks 192..703: pair_bias (8 i-tiles each, double-buffered)
__global__ void __launch_bounds__(256) fused_mid_kernel(
    const float* __restrict__ z,
    const float* __restrict__ Wq, const float* __restrict__ Wk,
    const float* __restrict__ Wv, const float* __restrict__ Wg,
    const float* __restrict__ bg) {
    extern __shared__ float smem[];
    if (blockIdx.x < 192) {
        int b = blockIdx.x;
        int mat = b / 48;
        int rem = b - mat * 48;
        int bx = rem % 6, by = rem / 6;
        qkvg_body(smem, mat, by * 64, bx * 64, Wq, Wk, Wv, Wg, bg);
        return;
    }
    // pair_bias role
    float* zbuf0 = smem;                 // 64 x ZST
    float* zbuf1 = zbuf0 + PB_TILE;      // 64 x ZST
    float* ws    = zbuf1 + PB_TILE;      // 16 x 128
    float* smean = ws + PB_WS;           // 64
    float* srstd = smean + 64;           // 64
    float* part  = srstd + 64;           // [4][32][9]
    __shared__ float cs_s[NH], cc_s[NH];

    int pb = blockIdx.x - 192;           // 0..511
    int j0 = (pb & 7) * 64;
    int i0 = (pb >> 3) * TILES_PER_BLOCK;
    int t = threadIdx.x;

    // stage weights + constants
    #pragma unroll
    for (int k = 0; k < PB_WS / 256; k++) ws[t + 256 * k] = g_gwT[t + 256 * k];
    if (t < NH) { cs_s[t] = g_colsum[t]; cc_s[t] = g_cconst[t]; }

    uint32_t zb0_u32 = (uint32_t)__cvta_generic_to_shared(zbuf0);
    uint32_t zb1_u32 = (uint32_t)__cvta_generic_to_shared(zbuf1);

    // prefetch tile 0
    pair_bias_stage(zb0_u32, z, i0, j0, t);
    CP_COMMIT();

    for (int tile = 0; tile < TILES_PER_BLOCK; tile++) {
        if (tile + 1 < TILES_PER_BLOCK) {
            pair_bias_stage((tile & 1) ? zb0_u32 : zb1_u32, z, i0 + tile + 1, j0, t);
            CP_COMMIT();
            CP_WAIT1();   // tile's buffer complete; next prefetch may stay in flight
        } else {
            CP_WAIT0();
        }
        __syncthreads();
        pair_bias_tile_compute((tile & 1) ? zbuf1 : zbuf0, ws, smean, srstd, part,
                               cs_s, cc_s, i0 + tile, j0);
    }
}

// ---------------- K3: attention (unchanged from R13) ----------------
__global__ void attn_kernel() {
    extern __shared__ float smem[];
    float* ks   = smem;
    float* vs   = ks + 512 * KST;
    float* qs   = vs + 512 * KST;
    float* wbuf = qs + 64 * KST;

    int h  = blockIdx.y;
    int q0 = blockIdx.x * 64;
    int tid = threadIdx.x, lane = tid & 31, warp = tid >> 5;

    for (int idx = tid; idx < 512 * 24; idx += 256) {
        int n = idx / 24, d = idx - n * 24;
        const float* row = g_qkvg + n * (4 * CS);
        ks[n * KST + d] = row[CS + h * HD + d];
        vs[n * KST + d] = row[2 * CS + h * HD + d];
    }
    for (int idx = tid; idx < 64 * 24; idx += 256) {
        int n = idx / 24, d = idx - n * 24;
        qs[n * KST + d] = g_qkvg[(q0 + n) * (4 * CS) + h * HD + d];
    }
    __syncthreads();

    for (int qp2 = 0; qp2 < 4; qp2++) {
        int r0 = warp * 8 + qp2 * 2;
        int qrow0 = q0 + r0, qrow1 = qrow0 + 1;

        ulonglong2 qa2[6], qb2[6];
        #pragma unroll
        for (int c = 0; c < 6; c++) {
            qa2[c] = *(const ulonglong2*)(qs + r0 * KST + c * 4);
            qb2[c] = *(const ulonglong2*)(qs + (r0 + 1) * KST + c * 4);
        }
        const float* brow0 = g_bias + ((size_t)h * NN + qrow0) * NN;
        const float* brow1 = g_bias + ((size_t)h * NN + qrow1) * NN;

        float e0[16], e1[16];
        float mx0 = -1e30f, mx1 = -1e30f;
        #pragma unroll
        for (int jj = 0; jj < 16; jj++) {
            int j = jj * 32 + lane;
            const ulonglong2* kp2 = (const ulonglong2*)(ks + j * KST);
            u64 s0a = 0, s0b = 0, s1a = 0, s1b = 0;
            #pragma unroll
            for (int c = 0; c < 6; c++) {
                ulonglong2 kv = kp2[c];
                if (c & 1) {
                    FFMA2(s0b, qa2[c].x, kv.x); FFMA2(s0b, qa2[c].y, kv.y);
                    FFMA2(s1b, qb2[c].x, kv.x); FFMA2(s1b, qb2[c].y, kv.y);
                } else {
                    FFMA2(s0a, qa2[c].x, kv.x); FFMA2(s0a, qa2[c].y, kv.y);
                    FFMA2(s1a, qb2[c].x, kv.x); FFMA2(s1a, qb2[c].y, kv.y);
                }
            }
            float s0 = (u64lo(s0a) + u64hi(s0a)) + (u64lo(s0b) + u64hi(s0b)) + brow0[j];
            float s1 = (u64lo(s1a) + u64hi(s1a)) + (u64lo(s1b) + u64hi(s1b)) + brow1[j];
            e0[jj] = s0; e1[jj] = s1;
            mx0 = fmaxf(mx0, s0); mx1 = fmaxf(mx1, s1);
        }
        #pragma unroll
        for (int o = 16; o > 0; o >>= 1) {
            mx0 = fmaxf(mx0, __shfl_xor_sync(0xFFFFFFFFu, mx0, o));
            mx1 = fmaxf(mx1, __shfl_xor_sync(0xFFFFFFFFu, mx1, o));
        }
        float sum0 = 0.f, sum1 = 0.f;
        #pragma unroll
        for (int jj = 0; jj < 16; jj++) {
            e0[jj] = __expf(e0[jj] - mx0); sum0 += e0[jj];
            e1[jj] = __expf(e1[jj] - mx1); sum1 += e1[jj];
        }
        #pragma unroll
        for (int o = 16; o > 0; o >>= 1) {
            sum0 += __shfl_xor_sync(0xFFFFFFFFu, sum0, o);
            sum1 += __shfl_xor_sync(0xFFFFFFFFu, sum1, o);
        }
        float inv0 = 1.f / sum0, inv1 = 1.f / sum1;

        u64 a0p[12] = {}, a1p[12] = {};
        #pragma unroll
        for (int jj = 0; jj < 16; jj++) {
            int j = jj * 32 + lane;
            const ulonglong2* vp2 = (const ulonglong2*)(vs + j * KST);
            u64 p0p, p1p;
            PACK2(p0p, e0[jj]);
            PACK2(p1p, e1[jj]);
            #pragma unroll
            for (int c = 0; c < 6; c++) {
                ulonglong2 vv = vp2[c];
                FFMA2(a0p[2 * c], p0p, vv.x); FFMA2(a0p[2 * c + 1], p0p, vv.y);
                FFMA2(a1p[2 * c], p1p, vv.x); FFMA2(a1p[2 * c + 1], p1p, vv.y);
            }
        }
        float* wb = wbuf + warp * 48;
        #pragma unroll
        for (int m = 0; m < 12; m++) {
            float l0 = u64lo(a0p[m]), h0 = u64hi(a0p[m]);
            float l1 = u64lo(a1p[m]), h1 = u64hi(a1p[m]);
            #pragma unroll
            for (int o = 16; o > 0; o >>= 1) {
                l0 += __shfl_xor_sync(0xFFFFFFFFu, l0, o);
                h0 += __shfl_xor_sync(0xFFFFFFFFu, h0, o);
                l1 += __shfl_xor_sync(0xFFFFFFFFu, l1, o);
                h1 += __shfl_xor_sync(0xFFFFFFFFu, h1, o);
            }
            if (lane == 0) {
                wb[2 * m] = l0; wb[2 * m + 1] = h0;
                wb[24 + 2 * m] = l1; wb[24 + 2 * m + 1] = h1;
            }
        }
        __syncwarp();
        if (lane < 24) {
            float ov0 = wb[lane] * inv0;
            float gv0 = g_qkvg[qrow0 * (4 * CS) + 3 * CS + h * HD + lane];
            g_att[qrow0 * CS + h * HD + lane] = ov0 * gv0;
            float ov1 = wb[24 + lane] * inv1;
            float gv1 = g_qkvg[qrow1 * (4 * CS) + 3 * CS + h * HD + lane];
            g_att[qrow1 * CS + h * HD + lane] = ov1 * gv1;
        }
        __syncwarp();
    }
}

// ---------------- K4: output projection — k-split x8, atomic accumulate ----------------
__global__ void outproj_kernel(const float* __restrict__ Wo, float* __restrict__ out) {
    __shared__ float As[16][64];
    __shared__ float Bs[16][68];
    int bm = blockIdx.y * 64, bn = blockIdx.x * 64;
    int kbase = blockIdx.z * 48;
    int tid = threadIdx.x;
    int tx = tid & 15, ty = tid >> 4;
    int arow = tid >> 2, acol4 = (tid & 3) * 4;
    int brow = tid >> 4, bcol4 = (tid & 15) * 4;
    float acc[4][4] = {};

    for (int k0 = kbase; k0 < kbase + 48; k0 += 16) {
        float4 av = *(const float4*)(g_att + (bm + arow) * CS + k0 + acol4);
        As[acol4 + 0][arow] = av.x;
        As[acol4 + 1][arow] = av.y;
        As[acol4 + 2][arow] = av.z;
        As[acol4 + 3][arow] = av.w;
        float4 bv = *(const float4*)(Wo + (k0 + brow) * CS + bn + bcol4);
        *(float4*)&Bs[brow][bcol4] = bv;
        __syncthreads();
        #pragma unroll
        for (int kk = 0; kk < 16; kk++) {
            float4 a4 = *(const float4*)&As[kk][ty * 4];
            float4 b4 = *(const float4*)&Bs[kk][tx * 4];
            float af[4] = {a4.x, a4.y, a4.z, a4.w};
            float bf[4] = {b4.x, b4.y, b4.z, b4.w};
            #pragma unroll
            for (int i = 0; i < 4; i++)
                #pragma unroll
                for (int j = 0; j < 4; j++)
                    acc[i][j] += af[i] * bf[j];
        }
        __syncthreads();
    }
    #pragma unroll
    for (int i = 0; i < 4; i++) {
        int row = bm + ty * 4 + i;
        float* o = out + row * CS + bn + tx * 4;
        #pragma unroll
        for (int j = 0; j < 4; j++)
            atomicAdd(&o[j], acc[i][j]);
    }
}

// ---------------- launch ----------------
extern "C" void kernel_launch(void* const* d_in, const int* in_sizes, int n_in,
                              void* d_out, int out_size) {
    (void)in_sizes; (void)n_in; (void)out_size;
    const float* a   = (const float*)d_in[0];
    const float* z   = (const float*)d_in[1];
    const float* g_a = (const float*)d_in[2];
    const float* b_a = (const float*)d_in[3];
    const float* g_z = (const float*)d_in[4];
    const float* b_z = (const float*)d_in[5];
    const float* Wz  = (const float*)d_in[6];
    const float* bz  = (const float*)d_in[7];
    const float* Wq  = (const float*)d_in[8];
    const float* Wk  = (const float*)d_in[9];
    const float* Wv  = (const float*)d_in[10];
    const float* Wg  = (const float*)d_in[11];
    const float* bg  = (const float*)d_in[12];
    const float* Wo  = (const float*)d_in[13];
    const float* bo  = (const float*)d_in[14];
    float* out = (float*)d_out;

    cudaFuncSetAttribute(fused_mid_kernel, cudaFuncAttributeMaxDynamicSharedMemorySize, PB_SMEM_BYTES);
    cudaFuncSetAttribute(attn_kernel, cudaFuncAttributeMaxDynamicSharedMemorySize, ATTN_SMEM_BYTES);

    prep_ln_kernel<<<NN + 1, 128>>>(a, g_a, b_a, g_z, b_z, Wz, bz, bo, out);
    fused_mid_kernel<<<192 + 512, 256, PB_SMEM_BYTES>>>(z, Wq, Wk, Wv, Wg, bg);
    attn_kernel<<<dim3(8, 16), 256, ATTN_SMEM_BYTES>>>();
    outproj_kernel<<<dim3(6, 8, 8), 256>>>(Wo, out);
}